// round 5
// baseline (speedup 1.0000x reference)
#include <cuda_runtime.h>
#include <math.h>

// Problem shape (fixed by reference setup_inputs)
#define BATCH 2048
#define NLABELS 50000
#define NTRIALS 64

// Early-exit layout: 1 warp serves 8 rows; each round probes 4 trials/row.
#define ROWS_PER_WARP 8
#define TRIALS_PER_ROUND 4
#define NUM_ROUNDS (NTRIALS / TRIALS_PER_ROUND)   // 16
#define WARPS_PER_BLOCK 8
#define THREADS_PER_BLOCK (WARPS_PER_BLOCK * 32)  // 256
#define ROWS_PER_BLOCK (WARPS_PER_BLOCK * ROWS_PER_WARP)  // 64
#define NUM_BLOCKS (BATCH / ROWS_PER_BLOCK)       // 32

// Scratch for deterministic single-kernel reduction (no allocations allowed).
__device__ float g_partials[NUM_BLOCKS];
// atomicInc with limit NUM_BLOCKS-1 wraps to 0 when the last block arrives ->
// counter automatically reset for the next graph replay.
__device__ unsigned int g_arrive = 0;

__global__ void __launch_bounds__(THREADS_PER_BLOCK)
warp_loss_earlyexit(const float* __restrict__ inp,
                    const int* __restrict__ pos_idx,
                    const int* __restrict__ neg_cands,
                    float* __restrict__ out)
{
    const int tid       = threadIdx.x;
    const int lane      = tid & 31;
    const int wid       = tid >> 5;
    const int row_local = lane >> 2;            // 0..7: which row in this warp
    const int sub       = lane & 3;             // 0..3: trial within round
    const int warp_glob = blockIdx.x * WARPS_PER_BLOCK + wid;
    const int row       = warp_glob * ROWS_PER_WARP + row_local;

    const long  base  = (long)row * NLABELS;
    const int   p     = __ldg(pos_idx + row);           // 8 distinct addrs/warp
    const float pos_s = __ldg(inp + base + p);          // 8 random gathers/warp
    const float thr   = pos_s - 1.0f;                   // margin>=0 <=> neg>=thr

    float loss     = 0.0f;                              // only sub==0 lane sets it
    bool  resolved = false;

    // Scan trials in chunks of 4; exit as soon as all 8 rows of this warp
    // have found their first accepted trial (P(extra round) ~= 2.6%).
    #pragma unroll 1
    for (int k = 0; k < NUM_ROUNDS; k++) {
        const int trial = k * TRIALS_PER_ROUND + sub;
        float neg = 0.0f;
        bool  okv = false;
        if (!resolved) {
            const int idx = __ldg(neg_cands + row * NTRIALS + trial);
            neg = __ldg(inp + base + idx);
            okv = (neg >= thr);
        }
        const unsigned acc = __ballot_sync(0xffffffffu, okv);
        const unsigned nib = (acc >> (row_local * 4)) & 0xFu;

        // Uniform shuffle (all lanes execute); result only used where valid.
        const int fin = nib ? (__ffs(nib) - 1) : 0;      // first accept in round
        const int src = row_local * 4 + fin;
        const float sel = __shfl_sync(0xffffffffu, neg, src);

        if (!resolved && nib) {
            if (sub == 0) {
                const int   first = k * TRIALS_PER_ROUND + fin;
                const float nt    = (float)(first + 1);
                const float L     = logf(floorf((float)(NLABELS - 1) / nt));
                loss = L * (1.0f - pos_s + sel);
            }
            resolved = true;
        }
        if (__all_sync(0xffffffffu, resolved)) break;
    }
    // Rows never resolved contribute 0 (reference: loss = 0 when !any_ok).

    // ---- warp reduction (fixed shuffle order -> deterministic) ----
    #pragma unroll
    for (int off = 16; off >= 1; off >>= 1)
        loss += __shfl_xor_sync(0xffffffffu, loss, off);

    __shared__ float s_warp[WARPS_PER_BLOCK];
    __shared__ bool  s_is_last;
    if (lane == 0) s_warp[wid] = loss;
    __syncthreads();

    if (tid == 0) {
        float sum = 0.0f;
        #pragma unroll
        for (int i = 0; i < WARPS_PER_BLOCK; i++) sum += s_warp[i];
        g_partials[blockIdx.x] = sum;
        __threadfence();
        unsigned old = atomicInc(&g_arrive, NUM_BLOCKS - 1);
        s_is_last = (old == NUM_BLOCKS - 1);
    }
    __syncthreads();

    // Last-arriving block: deterministic final sum of 32 partials.
    if (s_is_last && wid == 0) {
        float v = (lane < NUM_BLOCKS) ? g_partials[lane] : 0.0f;
        #pragma unroll
        for (int off = 16; off >= 1; off >>= 1)
            v += __shfl_xor_sync(0xffffffffu, v, off);
        if (lane == 0) out[0] = v;
    }
}

extern "C" void kernel_launch(void* const* d_in, const int* in_sizes, int n_in,
                              void* d_out, int out_size)
{
    // metadata order: input (f32 [B,Y]), target (i32, UNUSED), pos_idx (i32 [B]),
    //                 neg_cands (i32 [B,T]); output f32 [1]
    const float* inp     = (const float*)d_in[0];
    const int*   pos_idx = (const int*)d_in[2];
    const int*   neg     = (const int*)d_in[3];
    float*       out     = (float*)d_out;

    warp_loss_earlyexit<<<NUM_BLOCKS, THREADS_PER_BLOCK>>>(inp, pos_idx, neg, out);
}

// round 6
// speedup vs baseline: 1.4000x; 1.4000x over previous
#include <cuda_runtime.h>
#include <math.h>

// Problem shape (fixed by reference setup_inputs)
#define BATCH 2048
#define NLABELS 50000
#define NTRIALS 64

// One thread per (row, trial<8): probe 8 trials/row in ONE parallel wave.
// P(row needs more than 8 trials) ~ 0.24^8 ~ 1e-5 on this data; the fallback
// loop below keeps exactness for arbitrary inputs.
#define TRIALS_PROBE 8
#define ROWS_PER_WARP 4                          // 32 / 8
#define WARPS_PER_BLOCK 2
#define THREADS_PER_BLOCK (WARPS_PER_BLOCK * 32) // 64
#define ROWS_PER_BLOCK (WARPS_PER_BLOCK * ROWS_PER_WARP)  // 8
#define NUM_BLOCKS (BATCH / ROWS_PER_BLOCK)      // 256

// Scratch for deterministic single-kernel reduction (no allocations allowed).
__device__ float g_partials[NUM_BLOCKS];
// atomicInc with limit NUM_BLOCKS-1 wraps to 0 on the last arrival ->
// auto-reset for every graph replay.
__device__ unsigned int g_arrive = 0;

__global__ void __launch_bounds__(THREADS_PER_BLOCK)
warp_loss_probe8(const float* __restrict__ inp,
                 const int* __restrict__ pos_idx,
                 const int* __restrict__ neg_cands,
                 float* __restrict__ out)
{
    const int tid       = threadIdx.x;
    const int lane      = tid & 31;
    const int wid       = tid >> 5;
    const int row_local = lane >> 3;             // 0..3 : row within warp
    const int sub       = lane & 7;              // 0..7 : trial within probe
    const int row       = (blockIdx.x * WARPS_PER_BLOCK + wid) * ROWS_PER_WARP
                          + row_local;

    const long  base  = (long)row * NLABELS;
    const int   p     = __ldg(pos_idx + row);
    const float pos_s = __ldg(inp + base + p);          // 1 line per row
    const float thr   = pos_s - 1.0f;                   // margin>=0 <=> neg>=thr

    // ---- round 0: trials 0..7, fully parallel ----
    const int   idx0 = __ldg(neg_cands + row * NTRIALS + sub);   // coalesced-ish
    const float neg0 = __ldg(inp + base + idx0);                 // random gather
    unsigned acc = __ballot_sync(0xffffffffu, neg0 >= thr);
    unsigned oct = (acc >> (row_local * 8)) & 0xFFu;

    float loss     = 0.0f;
    bool  resolved = (oct != 0u);

    {
        const int   fin = oct ? (__ffs(oct) - 1) : 0;
        const float sel = __shfl_sync(0xffffffffu, neg0, row_local * 8 + fin);
        if (resolved && sub == 0) {
            const float nt = (float)(fin + 1);
            const float L  = logf(floorf((float)(NLABELS - 1) / nt));
            loss = L * (1.0f - pos_s + sel);
        }
    }

    // ---- fallback rounds (prob ~1e-5 per row): trials 8..63 in chunks of 8 ----
    if (!__all_sync(0xffffffffu, resolved)) {
        #pragma unroll 1
        for (int k = 1; k < NTRIALS / TRIALS_PROBE; k++) {
            const int trial = k * TRIALS_PROBE + sub;
            float neg = 0.0f;
            bool  okv = false;
            if (!resolved) {
                const int idx = __ldg(neg_cands + row * NTRIALS + trial);
                neg = __ldg(inp + base + idx);
                okv = (neg >= thr);
            }
            const unsigned a  = __ballot_sync(0xffffffffu, okv);
            const unsigned o8 = (a >> (row_local * 8)) & 0xFFu;
            const int   fin = o8 ? (__ffs(o8) - 1) : 0;
            const float sel = __shfl_sync(0xffffffffu, neg, row_local * 8 + fin);
            if (!resolved && o8) {
                if (sub == 0) {
                    const int   first = k * TRIALS_PROBE + fin;
                    const float nt    = (float)(first + 1);
                    const float L     = logf(floorf((float)(NLABELS - 1) / nt));
                    loss = L * (1.0f - pos_s + sel);
                }
                resolved = true;
            }
            if (__all_sync(0xffffffffu, resolved)) break;
        }
    }
    // Never-resolved rows contribute 0 (matches reference when !any_ok).

    // ---- deterministic reduction: warp shuffle -> block -> chip ----
    #pragma unroll
    for (int off = 16; off >= 1; off >>= 1)
        loss += __shfl_xor_sync(0xffffffffu, loss, off);

    __shared__ float s_warp[WARPS_PER_BLOCK];
    __shared__ bool  s_is_last;
    if (lane == 0) s_warp[wid] = loss;
    __syncthreads();

    if (tid == 0) {
        float sum = s_warp[0] + s_warp[1];
        g_partials[blockIdx.x] = sum;
        __threadfence();
        unsigned old = atomicInc(&g_arrive, NUM_BLOCKS - 1);
        s_is_last = (old == NUM_BLOCKS - 1);
    }
    __syncthreads();

    // Last block: fixed-order sum of 256 partials using warp 0.
    if (s_is_last && wid == 0) {
        float v = 0.0f;
        #pragma unroll
        for (int j = 0; j < NUM_BLOCKS / 32; j++)     // 8 strided reads, L2-hot
            v += g_partials[lane + j * 32];
        #pragma unroll
        for (int off = 16; off >= 1; off >>= 1)
            v += __shfl_xor_sync(0xffffffffu, v, off);
        if (lane == 0) out[0] = v;
    }
}

extern "C" void kernel_launch(void* const* d_in, const int* in_sizes, int n_in,
                              void* d_out, int out_size)
{
    // metadata order: input (f32 [B,Y]), target (i32, UNUSED), pos_idx (i32 [B]),
    //                 neg_cands (i32 [B,T]); output f32 [1]
    const float* inp     = (const float*)d_in[0];
    const int*   pos_idx = (const int*)d_in[2];
    const int*   neg     = (const int*)d_in[3];
    float*       out     = (float*)d_out;

    warp_loss_probe8<<<NUM_BLOCKS, THREADS_PER_BLOCK>>>(inp, pos_idx, neg, out);
}